// round 1
// baseline (speedup 1.0000x reference)
#include <cuda_runtime.h>
#include <math.h>

// Problem constants (fixed by the reference setup_inputs)
#define BB   2        // batch
#define CC   96       // feature channels
#define HH   256
#define WW   256
#define HWV  65536    // H*W
#define NDIR 4        // dir(2) * batch(2):  z = dir*2 + b

// ---------------- scratch (device globals; no allocation allowed) ----------
__device__ float g_m[NDIR * HWV];            // warp-diff metric input [dir][b][HW]
__device__ float g_metric[NDIR * HWV];       // final clipped metric
__device__ float g_buf1[NDIR * 64 * HWV];    // conv1 output
__device__ float g_buf2[NDIR * 64 * HWV];    // conv2 output
__device__ float g_acc[NDIR * 97 * HWV];     // splat accumulators (96 feat + 1 weight)

// ---------------------------------------------------------------------------
// Kernel 1: mL / mR  = mean_c |direct - backwarp(sampled, flow)|
// ---------------------------------------------------------------------------
__global__ void warpdiff_kernel(const float* __restrict__ biflow,
                                const float* __restrict__ fL,
                                const float* __restrict__ fR)
{
    int z   = blockIdx.y;            // dir*2 + b
    int dir = z >> 1, b = z & 1;
    int p   = blockIdx.x * 256 + threadIdx.x;
    int y   = p >> 8, x = p & 255;

    const float* flow = biflow + (size_t)(b * 4 + dir * 2) * HWV;
    float tx = (float)x + flow[p]        * 0.125f;
    float ty = (float)y + flow[HWV + p]  * 0.125f;
    float x0f = floorf(tx), y0f = floorf(ty);
    float ax = tx - x0f, ay = ty - y0f;
    int x0 = (int)x0f, y0 = (int)y0f;
    int x1 = x0 + 1, y1 = y0 + 1;

    float w00 = (1.f - ax) * (1.f - ay);
    float w10 = ax * (1.f - ay);
    float w01 = (1.f - ax) * ay;
    float w11 = ax * ay;
    bool vx0 = (x0 >= 0) & (x0 < WW), vx1 = (x1 >= 0) & (x1 < WW);
    bool vy0 = (y0 >= 0) & (y0 < HH), vy1 = (y1 >= 0) & (y1 < HH);
    w00 *= (vx0 & vy0) ? 1.f : 0.f;
    w10 *= (vx1 & vy0) ? 1.f : 0.f;
    w01 *= (vx0 & vy1) ? 1.f : 0.f;
    w11 *= (vx1 & vy1) ? 1.f : 0.f;
    int xc0 = min(max(x0, 0), WW - 1), xc1 = min(max(x1, 0), WW - 1);
    int yc0 = min(max(y0, 0), HH - 1), yc1 = min(max(y1, 0), HH - 1);
    int i00 = yc0 * WW + xc0, i10 = yc0 * WW + xc1;
    int i01 = yc1 * WW + xc0, i11 = yc1 * WW + xc1;

    const float* dct = (dir ? fR : fL) + (size_t)b * CC * HWV;  // direct
    const float* smp = (dir ? fL : fR) + (size_t)b * CC * HWV;  // sampled

    float s = 0.f;
    for (int c = 0; c < CC; c++) {
        const float* sp = smp + (size_t)c * HWV;
        float v = w00 * sp[i00] + w10 * sp[i10] + w01 * sp[i01] + w11 * sp[i11];
        s += fabsf(dct[(size_t)c * HWV + p] - v);
    }
    g_m[(size_t)z * HWV + p] = s * (1.f / (float)CC);
}

// ---------------------------------------------------------------------------
// Conv 3x3 SAME, 64 output channels, smem-tiled.
// FIRST: in = concat(metric(1), feat(96)) -> g_buf1
// else : in = g_buf1(64)                  -> g_buf2
// ---------------------------------------------------------------------------
template <bool FIRST, int CIN>
__global__ __launch_bounds__(256, 2)
void conv64_kernel(const float* __restrict__ fL,
                   const float* __restrict__ fR,
                   const float* __restrict__ w,
                   const float* __restrict__ bias)
{
    __shared__ float s_in[18 * 18];
    __shared__ float s_w[9 * 64];

    int z    = blockIdx.z;
    int dir  = z >> 1, b = z & 1;
    int tile = blockIdx.x;
    int ty0  = (tile >> 4) << 4;
    int tx0  = (tile & 15) << 4;
    int tid  = threadIdx.x;
    int ttx  = tid & 15, tty = tid >> 4;

    const float* feat = (dir ? fR : fL) + (size_t)b * CC * HWV;

    float acc[64];
#pragma unroll
    for (int i = 0; i < 64; i++) acc[i] = 0.f;

    for (int ic = 0; ic < CIN; ic++) {
        __syncthreads();
        // input tile 18x18 (with SAME zero border)
        for (int i = tid; i < 324; i += 256) {
            int r = i / 18, cc = i - r * 18;
            int gy = ty0 + r - 1, gx = tx0 + cc - 1;
            float v = 0.f;
            if (gy >= 0 && gy < HH && gx >= 0 && gx < WW) {
                int pix = gy * WW + gx;
                if (FIRST) {
                    v = (ic == 0) ? g_m[(size_t)z * HWV + pix]
                                  : feat[(size_t)(ic - 1) * HWV + pix];
                } else {
                    v = g_buf1[((size_t)z * 64 + ic) * HWV + pix];
                }
            }
            s_in[i] = v;
        }
        // weights for this ic: s_w[k*64 + oc] = w[(oc*CIN+ic)*9 + k]
        for (int i = tid; i < 576; i += 256) {
            int k = i >> 6, oc = i & 63;
            s_w[i] = w[((size_t)oc * CIN + ic) * 9 + k];
        }
        __syncthreads();

        float v[9];
#pragma unroll
        for (int ky = 0; ky < 3; ky++)
#pragma unroll
            for (int kx = 0; kx < 3; kx++)
                v[ky * 3 + kx] = s_in[(tty + ky) * 18 + ttx + kx];

#pragma unroll
        for (int k = 0; k < 9; k++) {
            float vk = v[k];
            const float4* wp = (const float4*)(s_w + (k << 6));
#pragma unroll
            for (int j = 0; j < 16; j++) {
                float4 w4 = wp[j];
                acc[j * 4 + 0] += w4.x * vk;
                acc[j * 4 + 1] += w4.y * vk;
                acc[j * 4 + 2] += w4.z * vk;
                acc[j * 4 + 3] += w4.w * vk;
            }
        }
    }

    int p = (ty0 + tty) * WW + tx0 + ttx;
    float* out = FIRST ? g_buf1 : g_buf2;
#pragma unroll
    for (int oc = 0; oc < 64; oc++) {
        float vv = acc[oc] + bias[oc];
        vv = vv > 0.f ? vv : 0.1f * vv;   // leaky 0.1
        out[((size_t)z * 64 + oc) * HWV + p] = vv;
    }
}

// ---------------------------------------------------------------------------
// Conv3: 64 -> 1, then metric = clip(alpha * (y+b), -20, 20)
// ---------------------------------------------------------------------------
__global__ void conv3_kernel(const float* __restrict__ w,
                             const float* __restrict__ bias,
                             const float* __restrict__ alpha)
{
    int z = blockIdx.z;
    int p = blockIdx.x * 256 + threadIdx.x;
    int y = p >> 8, x = p & 255;

    float sum = 0.f;
    for (int ic = 0; ic < 64; ic++) {
        const float* ip = g_buf2 + ((size_t)z * 64 + ic) * HWV;
        const float* wp = w + ic * 9;
#pragma unroll
        for (int ky = 0; ky < 3; ky++) {
            int gy = y + ky - 1;
            if (gy < 0 || gy >= HH) continue;
#pragma unroll
            for (int kx = 0; kx < 3; kx++) {
                int gx = x + kx - 1;
                if (gx < 0 || gx >= WW) continue;
                sum += ip[gy * WW + gx] * wp[ky * 3 + kx];
            }
        }
    }
    float m = alpha[0] * (sum + bias[0]);
    m = fminf(fmaxf(m, -20.f), 20.f);
    g_metric[(size_t)z * HWV + p] = m;
}

// ---------------------------------------------------------------------------
// Zero the splat accumulators
// ---------------------------------------------------------------------------
__global__ void zero_kernel()
{
    size_t n = (size_t)NDIR * 97 * HWV;
    for (size_t i = (size_t)blockIdx.x * blockDim.x + threadIdx.x; i < n;
         i += (size_t)gridDim.x * blockDim.x)
        g_acc[i] = 0.f;
}

// ---------------------------------------------------------------------------
// Softmax splat scatter: per (z, channel, pixel) -> 4 corner atomicAdds
// ---------------------------------------------------------------------------
__global__ void splat_kernel(const float* __restrict__ biflow,
                             const float* __restrict__ fL,
                             const float* __restrict__ fR)
{
    int z   = blockIdx.z;
    int dir = z >> 1, b = z & 1;
    int c   = blockIdx.y;                 // 0..96 (96 = weight channel)
    int p   = blockIdx.x * 256 + threadIdx.x;
    int y   = p >> 8, x = p & 255;

    const float* flow = biflow + (size_t)(b * 4 + dir * 2) * HWV;
    float tx = (float)x + flow[p]       * 0.125f;
    float ty = (float)y + flow[HWV + p] * 0.125f;
    float x0f = floorf(tx), y0f = floorf(ty);
    float ax = tx - x0f, ay = ty - y0f;
    int x0 = (int)x0f, y0 = (int)y0f;

    float m = expf(g_metric[(size_t)z * HWV + p]);
    float val = m;
    if (c < CC) {
        const float* f = (dir ? fR : fL) + (size_t)b * CC * HWV;
        val = f[(size_t)c * HWV + p] * m;
    }

    float* ap = g_acc + ((size_t)z * 97 + c) * HWV;
    float wts[4] = {(1.f - ax) * (1.f - ay), ax * (1.f - ay),
                    (1.f - ax) * ay,          ax * ay};
    int xs[4] = {x0, x0 + 1, x0,     x0 + 1};
    int ys[4] = {y0, y0,     y0 + 1, y0 + 1};
#pragma unroll
    for (int k = 0; k < 4; k++) {
        int xi = xs[k], yi = ys[k];
        if (xi >= 0 && xi < WW && yi >= 0 && yi < HH)
            atomicAdd(&ap[yi * WW + xi], val * wts[k]);
    }
}

// ---------------------------------------------------------------------------
// Normalize splat -> d_out warped sections
// d_out layout: warped_L [B,96,H,W] | warped_R [B,96,H,W] | cost [B,81,H,W]
// ---------------------------------------------------------------------------
__global__ void norm_kernel(float* __restrict__ out)
{
    int z   = blockIdx.z;
    int dir = z >> 1, b = z & 1;
    int c   = blockIdx.y;                 // 0..95
    int p   = blockIdx.x * 256 + threadIdx.x;

    float wsum = g_acc[((size_t)z * 97 + 96) * HWV + p];
    float v    = g_acc[((size_t)z * 97 + c)  * HWV + p] / (wsum + 1e-7f);
    out[(size_t)dir * BB * CC * HWV + ((size_t)b * CC + c) * HWV + p] = v;
}

// ---------------------------------------------------------------------------
// 81-channel PWC correlation (MD=4) + leaky 0.1
// ---------------------------------------------------------------------------
__global__ __launch_bounds__(256, 2)
void corr_kernel(const float* __restrict__ warped, float* __restrict__ cost)
{
    __shared__ float s_b[8][24][25];

    int b    = blockIdx.z;
    int tile = blockIdx.x;
    int ty0  = (tile >> 4) << 4;
    int tx0  = (tile & 15) << 4;
    int tid  = threadIdx.x;
    int ttx  = tid & 15, tty = tid >> 4;

    const float* A  = warped + (size_t)b * CC * HWV;                   // warped_L[b]
    const float* Bp = warped + ((size_t)BB * CC + (size_t)b * CC) * HWV;  // warped_R[b]

    float acc[81];
#pragma unroll
    for (int i = 0; i < 81; i++) acc[i] = 0.f;

    int p = (ty0 + tty) * WW + tx0 + ttx;

    for (int cc = 0; cc < CC; cc += 8) {
        __syncthreads();
        for (int i = tid; i < 8 * 24 * 24; i += 256) {
            int c = i / 576;
            int rem = i - c * 576;
            int r = rem / 24, col = rem - r * 24;
            int gy = ty0 + r - 4, gx = tx0 + col - 4;
            float v = 0.f;
            if (gy >= 0 && gy < HH && gx >= 0 && gx < WW)
                v = Bp[(size_t)(cc + c) * HWV + gy * WW + gx];
            s_b[c][r][col] = v;
        }
        __syncthreads();

#pragma unroll
        for (int c = 0; c < 8; c++) {
            float va = A[(size_t)(cc + c) * HWV + p];
#pragma unroll
            for (int dy = 0; dy < 9; dy++) {
                const float* row = &s_b[c][tty + dy][ttx];
#pragma unroll
                for (int dx = 0; dx < 9; dx++)
                    acc[dy * 9 + dx] += va * row[dx];
            }
        }
    }

#pragma unroll
    for (int d = 0; d < 81; d++) {
        float v = acc[d] * (1.f / (float)CC);
        v = v > 0.f ? v : 0.1f * v;
        cost[((size_t)b * 81 + d) * HWV + p] = v;
    }
}

// ---------------------------------------------------------------------------
extern "C" void kernel_launch(void* const* d_in, const int* in_sizes, int n_in,
                              void* d_out, int out_size)
{
    const float* biflow = (const float*)d_in[0];
    const float* fL     = (const float*)d_in[1];
    const float* fR     = (const float*)d_in[2];
    const float* alpha  = (const float*)d_in[3];
    const float* w1     = (const float*)d_in[4];
    const float* b1     = (const float*)d_in[5];
    const float* w2     = (const float*)d_in[6];
    const float* b2     = (const float*)d_in[7];
    const float* w3     = (const float*)d_in[8];
    const float* b3     = (const float*)d_in[9];
    float* out = (float*)d_out;
    (void)in_sizes; (void)n_in; (void)out_size;

    float* cost = out + (size_t)2 * BB * CC * HWV;

    // 1. warp diff metrics
    warpdiff_kernel<<<dim3(HWV / 256, NDIR), 256>>>(biflow, fL, fR);
    // 2. metric net
    conv64_kernel<true, 97><<<dim3(256, 1, NDIR), 256>>>(fL, fR, w1, b1);
    conv64_kernel<false, 64><<<dim3(256, 1, NDIR), 256>>>(fL, fR, w2, b2);
    conv3_kernel<<<dim3(HWV / 256, 1, NDIR), 256>>>(w3, b3, alpha);
    // 3. softmax splat
    zero_kernel<<<2048, 256>>>();
    splat_kernel<<<dim3(HWV / 256, 97, NDIR), 256>>>(biflow, fL, fR);
    norm_kernel<<<dim3(HWV / 256, CC, NDIR), 256>>>(out);
    // 4. correlation cost volume
    corr_kernel<<<dim3(256, 1, BB), 256>>>(out, cost);
}